// round 17
// baseline (speedup 1.0000x reference)
#include <cuda_runtime.h>
#include <cstdint>

#define NPTS 131072
#define BGR  64
#define NPG  2048
#define KNN  10
#define HD   64
#define CONV_BLOCKS (NPTS / 32)      // 4096
#define FULLMASK 0xffffffffu
#define PAIRNORM_EPS 1e-5f
#define ZPAD 65                      // s_z row stride (conflict-free scalar)

// spatial grid for kNN
#define GDIM  64
#define NCELL (GDIM * GDIM)          // 4096
#define XMIN  (-5.0f)
#define CELL  0.15625f               // 10/64
#define INVCELL 6.4f

// ---------------------------------------------------------------------------
// Device scratch
// ---------------------------------------------------------------------------
__device__ float2 d_spos[NPTS];             // positions sorted by cell
__device__ int    d_sidx[NPTS];             // slot -> original local idx
__device__ int    d_slotof[NPTS];           // original local idx -> slot
__device__ int    d_cellstart[BGR * (NCELL + 1)];
__device__ int    d_knn[NPTS * KNN];        // neighbor GLOBAL SLOTS, row = slot
__device__ float  d_Ya[NPTS * HD];          // Yraw layer-2, slot-indexed
__device__ float  d_Yb[NPTS * HD];          // Yraw layer-3, slot-indexed
__device__ float  d_partT[65 * CONV_BLOCKS];// transposed partials [feature][block]
__device__ float  d_sum[65];                // per-feature totals
__device__ float  d_mean[HD];
__device__ float  d_scaleInv;
__device__ float  d_beff[HD];
__device__ int    d_pool[BGR * HD];         // pooled max (float bits, z>=0)
__device__ unsigned d_rc;                   // redstat ticket (self-resetting)

// ---------------------------------------------------------------------------
// init: zero the pool accumulator
// ---------------------------------------------------------------------------
__global__ void init_kernel() {
    int i = blockIdx.x * blockDim.x + threadIdx.x;
    if (i < BGR * HD) d_pool[i] = 0;
}

// ---------------------------------------------------------------------------
// reorder: per-graph counting sort by 64x64 cell id.
// Within-cell order nondeterministic (atomics) but kNN selection is
// order-independent (lexicographic (d2, original idx)) -> deterministic.
// ---------------------------------------------------------------------------
__global__ __launch_bounds__(256) void reorder_kernel(const float2* __restrict__ pos) {
    __shared__ int hist[NCELL];
    __shared__ unsigned short skey[NPG];
    __shared__ int scanbuf[256];
    int g = blockIdx.x;
    int tid = threadIdx.x;
    int base = g * NPG;

    for (int c = tid; c < NCELL; c += 256) hist[c] = 0;
    __syncthreads();

    for (int t = tid; t < NPG; t += 256) {
        float2 p = pos[base + t];
        int cx = (int)((p.x - XMIN) * INVCELL);
        int cy = (int)((p.y - XMIN) * INVCELL);
        cx = cx < 0 ? 0 : (cx > GDIM - 1 ? GDIM - 1 : cx);
        cy = cy < 0 ? 0 : (cy > GDIM - 1 ? GDIM - 1 : cy);
        unsigned key = (unsigned)(cy * GDIM + cx);
        skey[t] = (unsigned short)key;
        atomicAdd(&hist[key], 1);
    }
    __syncthreads();

    int cb = tid * 16;
    int loc[16];
    int tot = 0;
#pragma unroll
    for (int i = 0; i < 16; i++) { loc[i] = hist[cb + i]; tot += loc[i]; }
    scanbuf[tid] = tot;
    __syncthreads();
    for (int off = 1; off < 256; off <<= 1) {
        int add = 0;
        if (tid >= off) add = scanbuf[tid - off];
        __syncthreads();
        scanbuf[tid] += add;
        __syncthreads();
    }
    int run = scanbuf[tid] - tot;
#pragma unroll
    for (int i = 0; i < 16; i++) {
        hist[cb + i] = run;
        run += loc[i];
    }
    __syncthreads();

    int* cs = d_cellstart + g * (NCELL + 1);
    for (int c = tid; c < NCELL; c += 256) cs[c] = hist[c];
    if (tid == 0) cs[NCELL] = NPG;
    __syncthreads();

    for (int t = tid; t < NPG; t += 256) {
        int key = skey[t];
        int rank = atomicAdd(&hist[key], 1);
        d_spos[base + rank] = pos[base + t];
        d_sidx[base + rank] = t;
        d_slotof[base + t] = rank;
    }
}

// ---------------------------------------------------------------------------
// kNN: r9 search core + WORK-STEALING schedule.
// 256 blocks (4/graph). Each block owns 16 interleaved query-warps
// (qw = i*4 + quarter); warps steal i from a smem counter, so heavy
// query-warps don't serialize behind a static assignment. Output per query
// written exactly once -> schedule cannot affect results.
// ---------------------------------------------------------------------------
#define INS2(da, db, ia, ib) { \
    if ((db < da) || (db == da && ib < ia)) { \
        float _t = da; da = db; db = _t; int _u = ia; ia = ib; ib = _u; } }

__global__ __launch_bounds__(256) void knn_kernel() {
    __shared__ float2 spos[NPG];          // 16 KB
    __shared__ int    sidx[NPG];          // 8 KB
    __shared__ int    scs[NCELL + 1];     // 16 KB
    __shared__ int    s_ctr;
    int g = blockIdx.x >> 2;
    int quarter = blockIdx.x & 3;
    int base = g * NPG;
    int tid = threadIdx.x;
    int lane = tid & 31;

    if (tid == 0) s_ctr = 0;
    for (int t = tid; t < NPG; t += 256) { spos[t] = d_spos[base + t]; sidx[t] = d_sidx[base + t]; }
    const int* gcs = d_cellstart + g * (NCELL + 1);
    for (int c = tid; c < NCELL + 1; c += 256) scs[c] = gcs[c];
    __syncthreads();

    const float INF = __int_as_float(0x7f800000);
    const int* so = d_slotof + base;

    while (true) {
        int i;
        if (lane == 0) i = atomicAdd(&s_ctr, 1);
        i = __shfl_sync(FULLMASK, i, 0);
        if (i >= 16) break;
        int qw = i * 4 + quarter;         // interleaved query-warp (0..63)
        int r = qw * 32 + lane;           // query slot
        float2 q = spos[r];

        int cx = (int)((q.x - XMIN) * INVCELL);
        int cy = (int)((q.y - XMIN) * INVCELL);
        cx = cx < 0 ? 0 : (cx > GDIM - 1 ? GDIM - 1 : cx);
        cy = cy < 0 ? 0 : (cy > GDIM - 1 ? GDIM - 1 : cy);

        float s0 = INF, s1 = INF, s2 = INF, s3 = INF, s4 = INF;
        float s5 = INF, s6 = INF, s7 = INF, s8 = INF, s9 = INF;
        int n0 = 0x7fffffff, n1 = n0, n2 = n0, n3 = n0, n4 = n0;
        int n5 = n0, n6 = n0, n7 = n0, n8 = n0, n9 = n0;

#define SCANRANGE(P0, P1) { \
    for (int _p = (P0); _p < (P1); _p++) { \
        float2 cp = spos[_p]; \
        float dx = q.x - cp.x; \
        float dy = q.y - cp.y; \
        float d2 = __fadd_rn(__fmul_rn(dx, dx), __fmul_rn(dy, dy)); \
        if (d2 <= s9 && _p != r) { \
            int oi = sidx[_p]; \
            if (d2 < s9 || oi < n9) { \
                s9 = d2; n9 = oi; \
                INS2(s8, s9, n8, n9); INS2(s7, s8, n7, n8); INS2(s6, s7, n6, n7); \
                INS2(s5, s6, n5, n6); INS2(s4, s5, n4, n5); INS2(s3, s4, n3, n4); \
                INS2(s2, s3, n2, n3); INS2(s1, s2, n1, n2); INS2(s0, s1, n0, n1); \
            } } } }

        for (int R = 0; R < GDIM; R++) {
            if (R >= 1) {
                float lox = XMIN + (float)(cx - R + 1) * CELL;
                float hix = XMIN + (float)(cx + R) * CELL;
                float loy = XMIN + (float)(cy - R + 1) * CELL;
                float hiy = XMIN + (float)(cy + R) * CELL;
                float bnd = fminf(fminf(q.x - lox, hix - q.x), fminf(q.y - loy, hiy - q.y));
                if (bnd > 0.f && bnd * bnd * 0.9999f > s9) break;
            }
            if (R == 0) {
                int c = cy * GDIM + cx;
                SCANRANGE(scs[c], scs[c + 1]);
            } else {
                int x0 = cx - R < 0 ? 0 : cx - R;
                int x1 = cx + R > GDIM - 1 ? GDIM - 1 : cx + R;
                if (cy - R >= 0) {
                    int c = (cy - R) * GDIM;
                    SCANRANGE(scs[c + x0], scs[c + x1 + 1]);
                }
                if (cy + R <= GDIM - 1) {
                    int c = (cy + R) * GDIM;
                    SCANRANGE(scs[c + x0], scs[c + x1 + 1]);
                }
                int y0 = cy - R + 1 < 0 ? 0 : cy - R + 1;
                int y1 = cy + R - 1 > GDIM - 1 ? GDIM - 1 : cy + R - 1;
                if (cx - R >= 0) {
                    for (int yy = y0; yy <= y1; yy++) {
                        int c = yy * GDIM + cx - R;
                        SCANRANGE(scs[c], scs[c + 1]);
                    }
                }
                if (cx + R <= GDIM - 1) {
                    for (int yy = y0; yy <= y1; yy++) {
                        int c = yy * GDIM + cx + R;
                        SCANRANGE(scs[c], scs[c + 1]);
                    }
                }
            }
        }

        int* op = d_knn + (base + r) * KNN;
        op[0] = base + so[n0]; op[1] = base + so[n1]; op[2] = base + so[n2];
        op[3] = base + so[n3]; op[4] = base + so[n4]; op[5] = base + so[n5];
        op[6] = base + so[n6]; op[7] = base + so[n7]; op[8] = base + so[n8];
        op[9] = base + so[n9];
    }
}

// ---------------------------------------------------------------------------
// block stats -> TRANSPOSED partials d_partT[feature][block]
// ---------------------------------------------------------------------------
__device__ __forceinline__ void block_stats(const float* s_z, float* s_red, int blockId) {
    int tid = threadIdx.x;
    if (tid < HD) {
        float s = 0.f, sq = 0.f;
#pragma unroll
        for (int r = 0; r < 32; r++) {
            float v = s_z[r * ZPAD + tid];
            s += v;
            sq = fmaf(v, v, sq);
        }
        d_partT[tid * CONV_BLOCKS + blockId] = s;
        s_red[tid] = sq;
    }
    __syncthreads();
    if (tid < 32) {
        float v = s_red[tid] + s_red[tid + 32];
#pragma unroll
        for (int off = 16; off > 0; off >>= 1)
            v += __shfl_down_sync(FULLMASK, v, off);
        if (tid == 0) d_partT[64 * CONV_BLOCKS + blockId] = v;
    }
}

// ---------------------------------------------------------------------------
// redstat: 65 blocks, coalesced column reduce; last block folds mean/inv/beff
// ---------------------------------------------------------------------------
__global__ __launch_bounds__(256) void redstat_kernel(const float* __restrict__ Wnext,
                                                      const float* __restrict__ bnext) {
    __shared__ float sred[256];
    __shared__ float smean[64];
    __shared__ int   s_last;
    int f = blockIdx.x;
    int tid = threadIdx.x;

    const float* col = d_partT + f * CONV_BLOCKS;
    float s = 0.f;
#pragma unroll
    for (int k = 0; k < CONV_BLOCKS / 256; k++) s += col[tid + k * 256];
    sred[tid] = s;
    __syncthreads();
    if (tid < 128) sred[tid] += sred[tid + 128];
    __syncthreads();
    if (tid < 64) sred[tid] += sred[tid + 64];
    __syncthreads();
    if (tid < 32) {
        float v = sred[tid] + sred[tid + 32];
#pragma unroll
        for (int off = 16; off > 0; off >>= 1)
            v += __shfl_down_sync(FULLMASK, v, off);
        if (tid == 0) d_sum[f] = v;
    }
    __threadfence();
    if (tid == 0) {
        unsigned t = atomicAdd(&d_rc, 1u);
        s_last = (t == 64u);
    }
    __syncthreads();
    if (!s_last) return;

    if (tid < 64) {
        float mean = d_sum[tid] * (1.0f / (float)NPTS);
        smean[tid] = mean;
        d_mean[tid] = mean;
    }
    __syncthreads();
    if (tid == 0) {
        float sq = d_sum[64];
        float ms = 0.f;
#pragma unroll 4
        for (int k = 0; k < 64; k++) ms = fmaf(smean[k], smean[k], ms);
        float denom = sq * (1.0f / (float)NPTS) - ms;
        d_scaleInv = 1.0f / sqrtf(PAIRNORM_EPS + denom);
        d_rc = 0;
    }
    __syncthreads();
    if (Wnext != nullptr && tid < 64) {
        float inv = d_scaleInv;
        float acc = 0.f;
#pragma unroll 4
        for (int k = 0; k < 64; k++) acc = fmaf(smean[k], Wnext[k * HD + tid], acc);
        d_beff[tid] = bnext[tid] - inv * acc;
    }
}

// ---------------------------------------------------------------------------
// epilogue GEMM (exact fp32): Yout[32x64] = s_z @ sW(64x64)
// ---------------------------------------------------------------------------
__device__ __forceinline__ void epilogue_gemm(const float* s_z, const float4* sW,
                                              float* Yout, int nodebase) {
    int tid = threadIdx.x;
    int row = tid & 31;
    int cg = tid >> 5;
    float4 a0 = make_float4(0.f, 0.f, 0.f, 0.f);
    float4 a1 = make_float4(0.f, 0.f, 0.f, 0.f);
    const float* zr = s_z + row * ZPAD;
#pragma unroll 4
    for (int k = 0; k < 64; k++) {
        float zk = zr[k];
        float4 w0 = sW[k * 16 + cg * 2];
        float4 w1 = sW[k * 16 + cg * 2 + 1];
        a0.x = fmaf(zk, w0.x, a0.x); a0.y = fmaf(zk, w0.y, a0.y);
        a0.z = fmaf(zk, w0.z, a0.z); a0.w = fmaf(zk, w0.w, a0.w);
        a1.x = fmaf(zk, w1.x, a1.x); a1.y = fmaf(zk, w1.y, a1.y);
        a1.z = fmaf(zk, w1.z, a1.z); a1.w = fmaf(zk, w1.w, a1.w);
    }
    float4* yo = (float4*)(Yout + (nodebase + row) * HD + cg * 8);
    yo[0] = a0;
    yo[1] = a1;
}

// ---------------------------------------------------------------------------
// convA (layer 1): 2-node edge staging; msg = rel @ W1 + b1, max + relu;
//   stats -> d_partT; FFMA epilogue Yraw2 = z @ W2x -> d_Ya
// ---------------------------------------------------------------------------
__global__ __launch_bounds__(256) void convA_kernel(const float* __restrict__ W1,
                                                    const float* __restrict__ b1,
                                                    const float* __restrict__ W2) {
    __shared__ float  s_z[32 * ZPAD];
    __shared__ float4 sW[1024];
    __shared__ float2 s_pj[8][2 * KNN];
    __shared__ float  s_red[64];
    int tid = threadIdx.x, lane = tid & 31, wid = tid >> 5;
    int f0 = lane * 2, f1 = f0 + 1;
    float wx0 = W1[f0],      wx1 = W1[f1];
    float wy0 = W1[HD + f0], wy1 = W1[HD + f1];
    float bb0 = b1[f0],      bb1 = b1[f1];
    int nodebase = blockIdx.x * 32;

    const float4* W2x4 = (const float4*)W2;
    for (int i = tid; i < 1024; i += 256) sW[i] = W2x4[i];

    for (int half = 0; half < 2; half++) {
        int nb = nodebase + wid * 4 + half * 2;
        if (lane < 2 * KNN) {
            int nd = nb + (lane >= KNN ? 1 : 0);
            int e = lane >= KNN ? lane - KNN : lane;
            int jj = d_knn[nd * KNN + e];
            s_pj[wid][lane] = d_spos[jj];
        }
        __syncwarp();
#pragma unroll
        for (int it = 0; it < 2; it++) {
            int node = nb + it;
            float2 pi = d_spos[node];
            float m0 = bb0, m1 = bb1;            // self edge rel=0
#pragma unroll
            for (int e = 0; e < KNN; e++) {
                float2 pj = s_pj[wid][it * KNN + e];
                float rx = pj.x - pi.x, ry = pj.y - pi.y;
                m0 = fmaxf(m0, fmaf(rx, wx0, fmaf(ry, wy0, bb0)));
                m1 = fmaxf(m1, fmaf(rx, wx1, fmaf(ry, wy1, bb1)));
            }
            int r = wid * 4 + half * 2 + it;
            s_z[r * ZPAD + f0] = fmaxf(m0, 0.f);
            s_z[r * ZPAD + f1] = fmaxf(m1, 0.f);
        }
        __syncwarp();
    }
    __syncthreads();
    block_stats(s_z, s_red, blockIdx.x);
    __syncthreads();
    epilogue_gemm(s_z, sW, d_Ya, nodebase);
}

// ---------------------------------------------------------------------------
// convB (layer 2): 2-node edge staging (20 gathers in flight), gather d_Ya;
//   stats -> d_partT; FFMA epilogue (W3) -> d_Yb
// ---------------------------------------------------------------------------
__global__ __launch_bounds__(256) void convB_kernel(const float* __restrict__ W2,
                                                    const float* __restrict__ W3) {
    __shared__ float  s_z[32 * ZPAD];
    __shared__ float4 sW[1024];
    __shared__ float2 s_pj[8][2 * KNN];
    __shared__ int    s_j[8][2 * KNN];
    __shared__ float  s_red[64];
    int tid = threadIdx.x, lane = tid & 31, wid = tid >> 5;
    int f0 = lane * 2, f1 = f0 + 1;
    float wx0 = W2[64 * HD + f0], wx1 = W2[64 * HD + f1];
    float wy0 = W2[65 * HD + f0], wy1 = W2[65 * HD + f1];
    float be0 = d_beff[f0], be1 = d_beff[f1];
    float inv = d_scaleInv;
    int nodebase = blockIdx.x * 32;

    const float4* W3x4 = (const float4*)W3;
    for (int i = tid; i < 1024; i += 256) sW[i] = W3x4[i];

    for (int half = 0; half < 2; half++) {
        int nb = nodebase + wid * 4 + half * 2;
        if (lane < 2 * KNN) {
            int nd = nb + (lane >= KNN ? 1 : 0);
            int e = lane >= KNN ? lane - KNN : lane;
            int jj = d_knn[nd * KNN + e];
            s_pj[wid][lane] = d_spos[jj];
            s_j[wid][lane] = jj;
        }
        __syncwarp();
#pragma unroll
        for (int it = 0; it < 2; it++) {
            int node = nb + it;
            float2 pi = d_spos[node];
            float2 ys = *(const float2*)(d_Ya + node * HD + f0);
            float m0 = fmaf(inv, ys.x, be0), m1 = fmaf(inv, ys.y, be1);
#pragma unroll
            for (int e = 0; e < KNN; e++) {
                float2 pj = s_pj[wid][it * KNN + e];
                int j = s_j[wid][it * KNN + e];
                float rx = pj.x - pi.x, ry = pj.y - pi.y;
                float2 yv = *(const float2*)(d_Ya + j * HD + f0);
                m0 = fmaxf(m0, fmaf(inv, yv.x, fmaf(rx, wx0, fmaf(ry, wy0, be0))));
                m1 = fmaxf(m1, fmaf(inv, yv.y, fmaf(rx, wx1, fmaf(ry, wy1, be1))));
            }
            int r = wid * 4 + half * 2 + it;
            s_z[r * ZPAD + f0] = fmaxf(m0, 0.f);
            s_z[r * ZPAD + f1] = fmaxf(m1, 0.f);
        }
        __syncwarp();
    }
    __syncthreads();
    block_stats(s_z, s_red, blockIdx.x);
    __syncthreads();
    epilogue_gemm(s_z, sW, d_Yb, nodebase);
}

// ---------------------------------------------------------------------------
// convC (layer 3): 2-node staging, gather d_Yb; stats; per-graph max pool
// ---------------------------------------------------------------------------
__global__ __launch_bounds__(256) void convC_kernel(const float* __restrict__ W3) {
    __shared__ float  s_z[32 * ZPAD];
    __shared__ float2 s_pj[8][2 * KNN];
    __shared__ int    s_j[8][2 * KNN];
    __shared__ float  s_red[64];
    int tid = threadIdx.x, lane = tid & 31, wid = tid >> 5;
    int f0 = lane * 2, f1 = f0 + 1;
    float wx0 = W3[64 * HD + f0], wx1 = W3[64 * HD + f1];
    float wy0 = W3[65 * HD + f0], wy1 = W3[65 * HD + f1];
    float be0 = d_beff[f0], be1 = d_beff[f1];
    float inv = d_scaleInv;
    int nodebase = blockIdx.x * 32;

    for (int half = 0; half < 2; half++) {
        int nb = nodebase + wid * 4 + half * 2;
        if (lane < 2 * KNN) {
            int nd = nb + (lane >= KNN ? 1 : 0);
            int e = lane >= KNN ? lane - KNN : lane;
            int jj = d_knn[nd * KNN + e];
            s_pj[wid][lane] = d_spos[jj];
            s_j[wid][lane] = jj;
        }
        __syncwarp();
#pragma unroll
        for (int it = 0; it < 2; it++) {
            int node = nb + it;
            float2 pi = d_spos[node];
            float2 ys = *(const float2*)(d_Yb + node * HD + f0);
            float m0 = fmaf(inv, ys.x, be0), m1 = fmaf(inv, ys.y, be1);
#pragma unroll
            for (int e = 0; e < KNN; e++) {
                float2 pj = s_pj[wid][it * KNN + e];
                int j = s_j[wid][it * KNN + e];
                float rx = pj.x - pi.x, ry = pj.y - pi.y;
                float2 yv = *(const float2*)(d_Yb + j * HD + f0);
                m0 = fmaxf(m0, fmaf(inv, yv.x, fmaf(rx, wx0, fmaf(ry, wy0, be0))));
                m1 = fmaxf(m1, fmaf(inv, yv.y, fmaf(rx, wx1, fmaf(ry, wy1, be1))));
            }
            int r = wid * 4 + half * 2 + it;
            s_z[r * ZPAD + f0] = fmaxf(m0, 0.f);
            s_z[r * ZPAD + f1] = fmaxf(m1, 0.f);
        }
        __syncwarp();
    }
    __syncthreads();
    block_stats(s_z, s_red, blockIdx.x);
    if (tid < HD) {
        float m = s_z[tid];
#pragma unroll
        for (int r = 1; r < 32; r++) m = fmaxf(m, s_z[r * ZPAD + tid]);
        int g = blockIdx.x >> 6;
        atomicMax(&d_pool[g * HD + tid], __float_as_int(m));
    }
}

// ---------------------------------------------------------------------------
// head: normalize pooled max on the fly; MLP -> out[64,2]
// ---------------------------------------------------------------------------
__global__ __launch_bounds__(128) void head_kernel(const float* __restrict__ Wl1,
                                                   const float* __restrict__ bl1,
                                                   const float* __restrict__ Wl2,
                                                   const float* __restrict__ bl2,
                                                   float* __restrict__ out) {
    __shared__ float t1[BGR * HD];
    __shared__ float sW[HD * HD];
    __shared__ float s_mean[64];
    int tid = threadIdx.x;
    float inv = d_scaleInv;

    if (tid < HD) s_mean[tid] = d_mean[tid];
    const float4* W4 = (const float4*)Wl1;
    float4* sW4 = (float4*)sW;
    for (int i = tid; i < HD * HD / 4; i += 128) sW4[i] = W4[i];
    __syncthreads();

    int g = tid >> 1, half = tid & 1;
    float acc[32];
#pragma unroll
    for (int c = 0; c < 32; c++) acc[c] = bl1[half * 32 + c];
    for (int k = 0; k < HD; k++) {
        float h = (__int_as_float(d_pool[g * HD + k]) - s_mean[k]) * inv;
        const float* wrow = sW + k * HD + half * 32;
#pragma unroll
        for (int c = 0; c < 32; c++) acc[c] = fmaf(h, wrow[c], acc[c]);
    }
#pragma unroll
    for (int c = 0; c < 32; c++) t1[g * HD + half * 32 + c] = fmaxf(acc[c], 0.f);
    __syncthreads();

    int gg = tid >> 1, o = tid & 1;
    float s = bl2[o];
    for (int k = 0; k < HD; k++) s = fmaf(t1[gg * HD + k], Wl2[k * 2 + o], s);
    out[gg * 2 + o] = s;
}

// ---------------------------------------------------------------------------
// launch — capture index 3 = convA
// ---------------------------------------------------------------------------
extern "C" void kernel_launch(void* const* d_in, const int* in_sizes, int n_in,
                              void* d_out, int out_size) {
    const float2* pos = (const float2*)d_in[0];
    const float* W1  = (const float*)d_in[2];
    const float* b1  = (const float*)d_in[3];
    const float* W2  = (const float*)d_in[4];
    const float* b2  = (const float*)d_in[5];
    const float* W3  = (const float*)d_in[6];
    const float* b3  = (const float*)d_in[7];
    const float* Wl1 = (const float*)d_in[8];
    const float* bl1 = (const float*)d_in[9];
    const float* Wl2 = (const float*)d_in[10];
    const float* bl2 = (const float*)d_in[11];
    float* out = (float*)d_out;

    init_kernel<<<16, 256>>>();                        // 0
    reorder_kernel<<<BGR, 256>>>(pos);                 // 1
    knn_kernel<<<BGR * 4, 256>>>();                    // 2
    convA_kernel<<<CONV_BLOCKS, 256>>>(W1, b1, W2);    // 3  <- profiled
    redstat_kernel<<<65, 256>>>(W2, b2);               // 4
    convB_kernel<<<CONV_BLOCKS, 256>>>(W2, W3);        // 5
    redstat_kernel<<<65, 256>>>(W3, b3);               // 6
    convC_kernel<<<CONV_BLOCKS, 256>>>(W3);            // 7
    redstat_kernel<<<65, 256>>>(nullptr, nullptr);     // 8
    head_kernel<<<1, 128>>>(Wl1, bl1, Wl2, bl2, out);  // 9
}